// round 5
// baseline (speedup 1.0000x reference)
#include <cuda_runtime.h>
#include <math.h>

#define BB 16
#define KK 5
#define NN 4096
#define DD 64
#define CC 16
#define BN (BB*NN)
#define EPS_LN 1e-5f
#define SCALE 0.125f

// ---------------- device scratch (allocation-free) ----------------
__device__ float g_featc[BN*CC];      // LN(feat_color)
__device__ float h_fk[BN*DD];         // LN(feat) @ w_k^T   (fused, fresh buffer)
__device__ float h_fv[BN*DD];         // LN(feat) @ w_v^T
__device__ float g_fg[KK*2];          // fg_pos
__device__ float g_lg[BB*KK*NN];      // logits (pre-softmax)
__device__ float g_isv[BB*KK*NN];     // 1/sigma_v
__device__ float g_mv[BB*KK*NN];      // mu_v
__device__ float g_att[BB*KK*NN];     // attn (softmax)
__device__ float g_w[BB*KK*NN];       // attn * inv_sigma_v
__device__ float h_qg[BB*KK*DD];      // (q @ w_mlp) * ln_kv_g
__device__ float h_qc[BB*KK*2];       // [const, sum(qg)]
__device__ float g_wmu[BB*KK];        // sum_n w*mu_v
__device__ float g_Tp[BB*8*KK*DD];    // partials of w@fv
__device__ float g_Tq[KK*8*BB*DD];    // partials of w@ge
__device__ float g_Cp[BB*8*KK*CC];    // partials of attn@featc
__device__ float g_slot[BB*KK*DD];
__device__ float g_wmT[DD*DD];        // transposed weights for coalesced matvec
__device__ float g_wresT[DD*DD];
__device__ float g_wihT[DD*3*DD];
__device__ float g_whhT[DD*3*DD];

// ---------------- precompute ----------------

__global__ void k_fgpos(const float* __restrict__ mask) {
    int k = blockIdx.x, t = threadIdx.x;
    float mx = 0.f, my = 0.f, s = 0.f;
    for (int n = t; n < NN; n += 256) {
        int h = n >> 6, w = n & 63;
        float m = mask[k*NN + n];
        mx += (-1.f + 2.f*w*(1.f/63.f))*m;
        my += (-1.f + 2.f*h*(1.f/63.f))*m;
        s += m;
    }
    __shared__ float sm[3][256];
    sm[0][t]=mx; sm[1][t]=my; sm[2][t]=s; __syncthreads();
    for (int o=128;o>0;o>>=1){
        if (t<o){ sm[0][t]+=sm[0][t+o]; sm[1][t]+=sm[1][t+o]; sm[2][t]+=sm[2][t+o]; }
        __syncthreads();
    }
    if (t==0){
        float inv = 1.f/(sm[2][0]+1e-5f);
        g_fg[k*2+0]=sm[0][0]*inv; g_fg[k*2+1]=sm[1][0]*inv;
    }
}

__global__ void k_lnc(const float* __restrict__ x, const float* __restrict__ g,
                      const float* __restrict__ b) {
    int idx = blockIdx.x*256 + threadIdx.x;
    int row = idx >> 4, lane = idx & 15;
    float v = x[row*CC + lane];
    float s = v;
    #pragma unroll
    for (int o=8;o>0;o>>=1) s += __shfl_xor_sync(0xffffffffu,s,o);
    float m = s*(1.f/16.f);
    float d = v-m;
    float s2 = d*d;
    #pragma unroll
    for (int o=8;o>0;o>>=1) s2 += __shfl_xor_sync(0xffffffffu,s2,o);
    float is = rsqrtf(s2*(1.f/16.f) + EPS_LN);
    g_featc[row*CC+lane] = d*is*g[lane] + b[lane];
}

// Fused: LN(feat) row-wise, then GEMM vs w_k^T and w_v^T. No intermediate buffer.
__global__ void k2_fkfv(const float* __restrict__ feat, const float* __restrict__ lng,
                        const float* __restrict__ lnb, const float* __restrict__ wk,
                        const float* __restrict__ wv) {
    __shared__ float As[64][65];
    __shared__ float Ws[64][65];
    __shared__ float gS[64], bS[64];
    int t = threadIdx.x;
    int row0 = blockIdx.x*64;
    if (t < 64){ gS[t]=lng[t]; bS[t]=lnb[t]; }
    const float4* ag = (const float4*)(feat + (size_t)row0*64);
    #pragma unroll
    for (int i=0;i<4;i++){
        int idx4 = t + i*256;
        float4 v = ag[idx4];
        int r = idx4 >> 4, d0 = (idx4 & 15)*4;
        As[r][d0]=v.x; As[r][d0+1]=v.y; As[r][d0+2]=v.z; As[r][d0+3]=v.w;
    }
    __syncthreads();
    // LayerNorm each row in place: 4 threads per row, 16 elems each.
    {
        int r = t>>2, p = t&3;
        float s = 0.f;
        #pragma unroll
        for (int i=0;i<16;i++) s += As[r][p*16+i];
        s += __shfl_xor_sync(0xffffffffu,s,1);
        s += __shfl_xor_sync(0xffffffffu,s,2);
        float m = s*(1.f/64.f);
        float s2 = 0.f;
        #pragma unroll
        for (int i=0;i<16;i++){ float d = As[r][p*16+i]-m; s2 += d*d; }
        s2 += __shfl_xor_sync(0xffffffffu,s2,1);
        s2 += __shfl_xor_sync(0xffffffffu,s2,2);
        float is = rsqrtf(s2*(1.f/64.f) + EPS_LN);
        #pragma unroll
        for (int i=0;i<16;i++){
            int e = p*16+i;
            As[r][e] = (As[r][e]-m)*is*gS[e] + bS[e];
        }
    }
    int ty = t >> 4, tx = t & 15;
    int r0 = ty*4, c0 = tx*4;
    #pragma unroll
    for (int ph=0; ph<2; ph++){
        const float4* wg = (const float4*)(ph ? wv : wk);
        __syncthreads();
        #pragma unroll
        for (int i=0;i<4;i++){
            int idx4 = t + i*256;
            float4 v = wg[idx4];
            int r = idx4 >> 4, d0 = (idx4 & 15)*4;
            Ws[r][d0]=v.x; Ws[r][d0+1]=v.y; Ws[r][d0+2]=v.z; Ws[r][d0+3]=v.w;
        }
        __syncthreads();
        float acc[4][4] = {};
        #pragma unroll 4
        for (int d=0; d<64; d++){
            float a[4], w4[4];
            #pragma unroll
            for (int i=0;i<4;i++) a[i] = As[r0+i][d];
            #pragma unroll
            for (int j=0;j<4;j++) w4[j] = Ws[c0+j][d];
            #pragma unroll
            for (int i=0;i<4;i++)
                #pragma unroll
                for (int j=0;j<4;j++) acc[i][j] += a[i]*w4[j];
        }
        float* out = ph ? h_fv : h_fk;
        #pragma unroll
        for (int i=0;i<4;i++)
            *(float4*)(out + (size_t)(row0+r0+i)*64 + c0) =
                make_float4(acc[i][0],acc[i][1],acc[i][2],acc[i][3]);
    }
}

__global__ void k_slotinit(const float* __restrict__ noise, const float* __restrict__ mu,
                           const float* __restrict__ ls) {
    int i = blockIdx.x*256 + threadIdx.x;
    int d = i & 63;
    g_slot[i] = mu[d] + expf(ls[d]) * noise[i];
}

__global__ void k_transp(const float* __restrict__ wm, const float* __restrict__ wres,
                         const float* __restrict__ wih, const float* __restrict__ whh) {
    int t = blockIdx.x*256 + threadIdx.x;
    if (t < 4096){
        int d = t >> 6, e = t & 63;
        g_wmT[e*64+d] = wm[t];
        g_wresT[e*64+d] = wres[t];
    }
    if (t < 192*64){
        int j = t >> 6, d = t & 63;
        g_wihT[d*192+j] = wih[t];
        g_whhT[d*192+j] = whh[t];
    }
}

// ---------------- per-iteration ----------------

// qg = (LN(slot)@w_q^T @ w_mlp) * ln_kv_g ; const cb = q.bm + qm.kvb ; sq = sum(qg)
__global__ void k2_q(const float* __restrict__ lnqg, const float* __restrict__ lnqb,
                     const float* __restrict__ wq,   const float* __restrict__ wm,
                     const float* __restrict__ bm,   const float* __restrict__ kvg,
                     const float* __restrict__ kvb) {
    __shared__ float WQ[64][65], WM[64][65];
    __shared__ float lnrow[4][64], qrow[4][64];
    __shared__ float red[4][2], red2[4][2];
    int x = threadIdx.x, y = threadIdx.y;
    int t = y*64 + x;
    for (int i=t;i<4096;i+=256){ WQ[i>>6][i&63]=wq[i]; WM[i>>6][i&63]=wm[i]; }
    int row = blockIdx.x*4 + y;
    float sv = g_slot[row*64+x];
    float s = sv;
    #pragma unroll
    for (int o=16;o>0;o>>=1) s += __shfl_xor_sync(0xffffffffu,s,o);
    if ((x&31)==0) red[y][x>>5]=s;
    __syncthreads();
    float m = (red[y][0]+red[y][1])*(1.f/64.f);
    float d = sv - m;
    float s2 = d*d;
    #pragma unroll
    for (int o=16;o>0;o>>=1) s2 += __shfl_xor_sync(0xffffffffu,s2,o);
    if ((x&31)==0) red2[y][x>>5]=s2;
    __syncthreads();
    float is = rsqrtf((red2[y][0]+red2[y][1])*(1.f/64.f) + EPS_LN);
    lnrow[y][x] = d*is*lnqg[x] + lnqb[x];
    __syncthreads();
    float q = 0.f;
    #pragma unroll 8
    for (int j=0;j<64;j++) q += lnrow[y][j]*WQ[x][j];
    qrow[y][x] = q;
    __syncthreads();
    float qm = 0.f;
    #pragma unroll 8
    for (int j=0;j<64;j++) qm += qrow[y][j]*WM[j][x];
    float qgv = qm*kvg[x];
    h_qg[row*64+x] = qgv;
    float c1 = q*bm[x] + qm*kvb[x];
    float c2 = qgv;
    #pragma unroll
    for (int o=16;o>0;o>>=1){ c1+=__shfl_xor_sync(0xffffffffu,c1,o); c2+=__shfl_xor_sync(0xffffffffu,c2,o); }
    __syncthreads();
    if ((x&31)==0){ red[y][x>>5]=c1; red2[y][x>>5]=c2; }
    __syncthreads();
    if (x==0){ h_qc[row*2+0]=red[y][0]+red[y][1]; h_qc[row*2+1]=red2[y][0]+red2[y][1]; }
}

// Fused stats+logits with ge computed INLINE from w_grid/fg (no ge buffer).
// Grid (NN/64, BB), 256 thr; thread: n = t>>2 (64 rows), p = t&3 (16 elems each).
__global__ void k2_logits(const float* __restrict__ wgr, const float* __restrict__ bgr) {
    __shared__ float wg0S[64], wg1S[64], bgS[64];
    __shared__ float qgS[KK][64];
    __shared__ float qcS[KK][2];
    __shared__ float fgS[KK*2];
    int b = blockIdx.y, n0 = blockIdx.x*64, t = threadIdx.x;
    if (t < 64){
        wg0S[t] = wgr[t*4+0] - wgr[t*4+2];
        wg1S[t] = wgr[t*4+1] - wgr[t*4+3];
        bgS[t]  = bgr[t];
    }
    for (int i=t;i<KK*64;i+=256) qgS[i>>6][i&63] = h_qg[(b*KK + (i>>6))*64 + (i&63)];
    if (t < KK*2) qcS[t>>1][t&1] = h_qc[(b*KK + (t>>1))*2 + (t&1)];
    if (t < KK*2) fgS[t] = g_fg[t];
    int n = t>>2, p = t&3;
    int ng = n0 + n;
    float gx = -1.f + 2.f*(ng & 63)*(1.f/63.f);
    float gy = -1.f + 2.f*(ng >> 6)*(1.f/63.f);
    float4 fk4[4], fv4[4];
    const float4* fkg = (const float4*)(h_fk + (size_t)(b*NN+ng)*64) + p*4;
    const float4* fvg = (const float4*)(h_fv + (size_t)(b*NN+ng)*64) + p*4;
    #pragma unroll
    for (int i=0;i<4;i++){ fk4[i]=fkg[i]; fv4[i]=fvg[i]; }
    __syncthreads();
    for (int k=0;k<KK;k++){
        float r0 = gx - fgS[k*2+0];
        float r1 = gy - fgS[k*2+1];
        float su=0.f, su2=0.f, dq=0.f, sv=0.f, sv2=0.f;
        #pragma unroll
        for (int i=0;i<4;i++){
            int e0 = p*16 + i*4;
            float fkx[4] = {fk4[i].x, fk4[i].y, fk4[i].z, fk4[i].w};
            float fvx[4] = {fv4[i].x, fv4[i].y, fv4[i].z, fv4[i].w};
            #pragma unroll
            for (int j=0;j<4;j++){
                int e = e0+j;
                float ge = wg0S[e]*r0 + wg1S[e]*r1 + bgS[e];
                float u = fkx[j] + ge;
                float v = fvx[j] + ge;
                su += u; su2 += u*u;
                dq += qgS[k][e]*u;
                sv += v; sv2 += v*v;
            }
        }
        su += __shfl_xor_sync(0xffffffffu,su,1);  su += __shfl_xor_sync(0xffffffffu,su,2);
        su2+= __shfl_xor_sync(0xffffffffu,su2,1); su2+= __shfl_xor_sync(0xffffffffu,su2,2);
        dq += __shfl_xor_sync(0xffffffffu,dq,1);  dq += __shfl_xor_sync(0xffffffffu,dq,2);
        sv += __shfl_xor_sync(0xffffffffu,sv,1);  sv += __shfl_xor_sync(0xffffffffu,sv,2);
        sv2+= __shfl_xor_sync(0xffffffffu,sv2,1); sv2+= __shfl_xor_sync(0xffffffffu,sv2,2);
        if (p==0){
            size_t idx = (size_t)(b*KK+k)*NN + ng;
            float m = su*(1.f/64.f);
            float var = su2*(1.f/64.f) - m*m;
            float is = rsqrtf(var + EPS_LN);
            g_lg[idx] = SCALE*( is*(dq - m*qcS[k][1]) + qcS[k][0] );
            float mv = sv*(1.f/64.f);
            float varv = sv2*(1.f/64.f) - mv*mv;
            g_isv[idx] = rsqrtf(varv + EPS_LN);
            g_mv[idx] = mv;
        }
    }
}

__global__ void k_smax() {
    int k = blockIdx.x, b = blockIdx.y, r = b*KK+k, t = threadIdx.x;
    size_t base = (size_t)r*NN;
    float lg[16];
    float mx = -1e30f;
    #pragma unroll
    for (int j=0;j<16;j++){
        lg[j] = g_lg[base + j*256 + t];
        mx = fmaxf(mx, lg[j]);
    }
    __shared__ float sred[8], sred2[8];
    #pragma unroll
    for (int o=16;o>0;o>>=1) mx = fmaxf(mx, __shfl_xor_sync(0xffffffffu,mx,o));
    if ((t&31)==0) sred[t>>5] = mx;
    __syncthreads();
    mx = sred[0];
    #pragma unroll
    for (int i=1;i<8;i++) mx = fmaxf(mx, sred[i]);
    float se = 0.f;
    #pragma unroll
    for (int j=0;j<16;j++){ lg[j] = expf(lg[j]-mx); se += lg[j]; }
    float ss = se;
    #pragma unroll
    for (int o=16;o>0;o>>=1) ss += __shfl_xor_sync(0xffffffffu,ss,o);
    if ((t&31)==0) sred2[t>>5] = ss;
    __syncthreads();
    ss = 0.f;
    #pragma unroll
    for (int i=0;i<8;i++) ss += sred2[i];
    float inv = 1.f/ss;
    float wmu = 0.f;
    #pragma unroll
    for (int j=0;j<16;j++){
        size_t idx = base + j*256 + t;
        float a = lg[j]*inv;
        float w = a*g_isv[idx];
        g_att[idx] = a;
        g_w[idx] = w;
        wmu += w*g_mv[idx];
    }
    #pragma unroll
    for (int o=16;o>0;o>>=1) wmu += __shfl_xor_sync(0xffffffffu,wmu,o);
    __syncthreads();
    if ((t&31)==0) sred[t>>5] = wmu;
    __syncthreads();
    if (t==0){
        float s = 0.f;
        #pragma unroll
        for (int i=0;i<8;i++) s += sred[i];
        g_wmu[r] = s;
    }
}

__global__ void k_updF() {
    __shared__ float wS[KK][512];
    __shared__ float part[4][KK][64];
    int seg = blockIdx.x, b = blockIdx.y, t = threadIdx.x;
    int nbase = seg*512;
    for (int i=t;i<KK*512;i+=256){
        int k=i>>9, n=i&511;
        wS[k][n] = g_w[(size_t)(b*KK+k)*NN + nbase+n];
    }
    __syncthreads();
    int e = t & 63, q = t >> 6;
    float acc[KK] = {};
    for (int n=q*128; n<q*128+128; n++){
        float fv = h_fv[(size_t)(b*NN+nbase+n)*64 + e];
        #pragma unroll
        for (int k=0;k<KK;k++) acc[k] += wS[k][n]*fv;
    }
    #pragma unroll
    for (int k=0;k<KK;k++) part[q][k][e] = acc[k];
    __syncthreads();
    for (int i=t;i<KK*64;i+=256){
        int k=i>>6, ee=i&63;
        float s = part[0][k][ee]+part[1][k][ee]+part[2][k][ee]+part[3][k][ee];
        g_Tp[(size_t)((b*8+seg)*KK+k)*64 + ee] = s;
    }
}

// w @ ge with ge computed inline per (k, n, e).
__global__ void k2_updG(const float* __restrict__ wgr, const float* __restrict__ bgr) {
    __shared__ float wS[BB][512];
    __shared__ float part[BB][64];
    int seg = blockIdx.x, k = blockIdx.y, t = threadIdx.x;
    int nbase = seg*512;
    for (int i=t;i<BB*512;i+=256){
        int b=i>>9, n=i&511;
        wS[b][n] = g_w[(size_t)(b*KK+k)*NN + nbase+n];
    }
    for (int i=t;i<BB*64;i+=256) ((float*)part)[i] = 0.f;
    __syncthreads();
    int e = t & 63, q = t >> 6;
    float w0 = wgr[e*4+0] - wgr[e*4+2];
    float w1 = wgr[e*4+1] - wgr[e*4+3];
    float bg = bgr[e];
    float fgx = g_fg[k*2+0], fgy = g_fg[k*2+1];
    float acc[BB] = {};
    for (int n=q*128; n<q*128+128; n++){
        int ng = nbase + n;
        float r0 = (-1.f + 2.f*(ng & 63)*(1.f/63.f)) - fgx;
        float r1 = (-1.f + 2.f*(ng >> 6)*(1.f/63.f)) - fgy;
        float gv = w0*r0 + w1*r1 + bg;
        #pragma unroll
        for (int b=0;b<BB;b++) acc[b] += wS[b][n]*gv;
    }
    for (int qq=0;qq<4;qq++){
        if (q==qq){
            #pragma unroll
            for (int b=0;b<BB;b++) part[b][e] += acc[b];
        }
        __syncthreads();
    }
    for (int i=t;i<BB*64;i+=256){
        int b=i>>6, ee=i&63;
        g_Tq[(size_t)((k*8+seg)*BB+b)*64 + ee] = part[b][ee];
    }
}

__global__ void k_upd(const float* __restrict__ kvg, const float* __restrict__ kvb,
                      const float* __restrict__ bm,  const float* __restrict__ bih,
                      const float* __restrict__ bhh, const float* __restrict__ resg,
                      const float* __restrict__ resb,const float* __restrict__ bres) {
    __shared__ float lnsum[4][64], upds[4][64], hps[4][64], lns[4][64];
    __shared__ float red[4][2], red2[4][2];
    int x = threadIdx.x, y = threadIdx.y;
    int rrow = blockIdx.x*4 + y;
    int b = rrow/KK, k = rrow%KK;
    float T = 0.f;
    #pragma unroll
    for (int seg=0;seg<8;seg++){
        T += g_Tp[(size_t)((b*8+seg)*KK+k)*64 + x];
        T += g_Tq[(size_t)((k*8+seg)*BB+b)*64 + x];
    }
    T -= g_wmu[rrow];
    lnsum[y][x] = kvg[x]*T + kvb[x];
    float hp = g_slot[rrow*64+x];
    hps[y][x] = hp;
    __syncthreads();
    float upd = bm[x];
    #pragma unroll 8
    for (int e=0;e<64;e++) upd += g_wmT[e*64+x]*lnsum[y][e];
    upds[y][x] = upd;
    __syncthreads();
    float gir = bih[x], giz = bih[64+x], gin = bih[128+x];
    float ghr = bhh[x], ghz = bhh[64+x], ghn = bhh[128+x];
    #pragma unroll 4
    for (int d=0;d<64;d++){
        float u = upds[y][d], h = hps[y][d];
        const float* wiT = g_wihT + d*192;
        const float* whT = g_whhT + d*192;
        gir += wiT[x]*u;     giz += wiT[64+x]*u;  gin += wiT[128+x]*u;
        ghr += whT[x]*h;     ghz += whT[64+x]*h;  ghn += whT[128+x]*h;
    }
    float rg = 1.f/(1.f+expf(-(gir+ghr)));
    float z  = 1.f/(1.f+expf(-(giz+ghz)));
    float nn = tanhf(gin + rg*ghn);
    float hnew = (1.f-z)*nn + z*hp;
    float s = hnew;
    #pragma unroll
    for (int o=16;o>0;o>>=1) s += __shfl_xor_sync(0xffffffffu,s,o);
    if ((x&31)==0) red[y][x>>5]=s;
    __syncthreads();
    float m = (red[y][0]+red[y][1])*(1.f/64.f);
    float dd = hnew - m;
    float s2 = dd*dd;
    #pragma unroll
    for (int o=16;o>0;o>>=1) s2 += __shfl_xor_sync(0xffffffffu,s2,o);
    if ((x&31)==0) red2[y][x>>5]=s2;
    __syncthreads();
    float is = rsqrtf((red2[y][0]+red2[y][1])*(1.f/64.f) + EPS_LN);
    lns[y][x] = dd*is*resg[x] + resb[x];
    __syncthreads();
    float outv = bres[x] + hp;
    #pragma unroll 8
    for (int e=0;e<64;e++) outv += g_wresT[e*64+x]*lns[y][e];
    g_slot[rrow*64+x] = outv;
}

// ---------------- epilogue ----------------

__global__ void k_color() {
    __shared__ float aS[KK][512];
    __shared__ float part2[16][KK][CC];
    int seg = blockIdx.x, b = blockIdx.y, t = threadIdx.x;
    int nbase = seg*512;
    for (int i=t;i<KK*512;i+=256){
        int k=i>>9, n=i&511;
        aS[k][n] = g_att[(size_t)(b*KK+k)*NN + nbase+n];
    }
    __syncthreads();
    int c = t & 15, q = t >> 4;
    float acc[KK] = {};
    for (int n=q*32; n<q*32+32; n++){
        float fc = g_featc[(size_t)(b*NN+nbase+n)*CC + c];
        #pragma unroll
        for (int k=0;k<KK;k++) acc[k] += aS[k][n]*fc;
    }
    #pragma unroll
    for (int k=0;k<KK;k++) part2[q][k][c] = acc[k];
    __syncthreads();
    if (t < KK*CC){
        int k = t>>4, cc = t&15;
        float s = 0.f;
        #pragma unroll
        for (int qq=0;qq<16;qq++) s += part2[qq][k][cc];
        g_Cp[(size_t)((b*8+seg)*KK+k)*CC + cc] = s;
    }
}

__global__ void k_outslot(float* __restrict__ out) {
    int t = threadIdx.x;
    for (int i=t; i<80*80; i+=256){
        int r = i/80, d = i%80;
        float v;
        if (d < 64) v = g_slot[r*64+d];
        else {
            int c = d-64, b = r/KK, k = r%KK;
            v = 0.f;
            #pragma unroll
            for (int seg=0;seg<8;seg++) v += g_Cp[(size_t)((b*8+seg)*KK+k)*CC + c];
        }
        out[i] = v;
    }
    if (t < 160){
        int r = t>>1, k = r%KK;
        out[6400 + t] = g_fg[k*2 + (t&1)];
    }
}

__global__ void k_attnnorm(float* __restrict__ out) {
    int k = blockIdx.x, b = blockIdx.y, r = b*KK+k, t = threadIdx.x;
    size_t base = (size_t)r*NN;
    float mn = 1e30f, mx = -1e30f;
    float a[16];
    #pragma unroll
    for (int j=0;j<16;j++){
        a[j] = g_att[base + j*256 + t];
        mn = fminf(mn, a[j]); mx = fmaxf(mx, a[j]);
    }
    __shared__ float sred[8], sred2[8];
    #pragma unroll
    for (int o=16;o>0;o>>=1){
        mn = fminf(mn, __shfl_xor_sync(0xffffffffu,mn,o));
        mx = fmaxf(mx, __shfl_xor_sync(0xffffffffu,mx,o));
    }
    if ((t&31)==0){ sred[t>>5]=mn; sred2[t>>5]=mx; }
    __syncthreads();
    mn = sred[0]; mx = sred2[0];
    #pragma unroll
    for (int i=1;i<8;i++){ mn = fminf(mn, sred[i]); mx = fmaxf(mx, sred2[i]); }
    float inv = 1.f/(mx-mn+1e-5f);
    #pragma unroll
    for (int j=0;j<16;j++)
        out[6560 + base + j*256 + t] = (a[j]-mn)*inv;
}

// ---------------- launch ----------------

extern "C" void kernel_launch(void* const* d_in, const int* in_sizes, int n_in,
                              void* d_out, int out_size) {
    const float* feat  = (const float*)d_in[0];
    const float* featc = (const float*)d_in[1];
    const float* mask  = (const float*)d_in[2];
    const float* noise = (const float*)d_in[3];
    const float* mu    = (const float*)d_in[4];
    const float* ls    = (const float*)d_in[5];
    const float* wgrid = (const float*)d_in[6];
    const float* bgrid = (const float*)d_in[7];
    const float* wk    = (const float*)d_in[8];
    const float* wv    = (const float*)d_in[9];
    const float* kvg   = (const float*)d_in[10];
    const float* kvb   = (const float*)d_in[11];
    const float* wmlp  = (const float*)d_in[12];
    const float* bmlp  = (const float*)d_in[13];
    const float* qg_   = (const float*)d_in[14];
    const float* qb_   = (const float*)d_in[15];
    const float* wq    = (const float*)d_in[16];
    const float* wih   = (const float*)d_in[17];
    const float* whh   = (const float*)d_in[18];
    const float* bih   = (const float*)d_in[19];
    const float* bhh   = (const float*)d_in[20];
    const float* fg_   = (const float*)d_in[21];
    const float* fb_   = (const float*)d_in[22];
    const float* cg_   = (const float*)d_in[23];
    const float* cb_   = (const float*)d_in[24];
    const float* rg_   = (const float*)d_in[25];
    const float* rb_   = (const float*)d_in[26];
    const float* wres  = (const float*)d_in[27];
    const float* bres  = (const float*)d_in[28];
    float* out = (float*)d_out;

    k_fgpos<<<KK,256>>>(mask);
    k_lnc<<<BN/16, 256>>>(featc, cg_, cb_);
    k2_fkfv<<<BN/64, 256>>>(feat, fg_, fb_, wk, wv);
    k_slotinit<<<BB*KK*DD/256, 256>>>(noise, mu, ls);
    k_transp<<<48, 256>>>(wmlp, wres, wih, whh);

    for (int it=0; it<4; it++){
        k2_q<<<20, dim3(64,4)>>>(qg_, qb_, wq, wmlp, bmlp, kvg, kvb);
        k2_logits<<<dim3(NN/64, BB), 256>>>(wgrid, bgrid);
        k_smax<<<dim3(KK, BB), 256>>>();
        if (it < 3){
            k_updF<<<dim3(8, BB), 256>>>();
            k2_updG<<<dim3(8, KK), 256>>>(wgrid, bgrid);
            k_upd<<<20, dim3(64,4)>>>(kvg, kvb, bmlp, bih, bhh, rg_, rb_, bres);
        }
    }
    k_color<<<dim3(8, BB), 256>>>();
    k_outslot<<<1, 256>>>(out);
    k_attnnorm<<<dim3(KK, BB), 256>>>(out);
}

// round 6
// speedup vs baseline: 1.2649x; 1.2649x over previous
#include <cuda_runtime.h>
#include <math.h>

#define BB 16
#define KK 5
#define NN 4096
#define DD 64
#define CC 16
#define BN (BB*NN)
#define EPS_LN 1e-5f
#define SCALE 0.125f

// ---------------- device scratch (allocation-free) ----------------
__device__ float g_featc[BN*CC];      // LN(feat_color)
__device__ float h_fk[BN*DD];         // LN(feat) @ w_k^T
__device__ float h_fv[BN*DD];         // LN(feat) @ w_v^T
__device__ float g_stK[BN*8];         // per (b,n): Sfk, S2fk, fk.wg0, fk.wg1, fk.bg
__device__ float g_stV[BN*8];         // same for fv
__device__ float g_fg[KK*2];          // fg_pos
__device__ float g_gsc[9];            // Sg0,Sg1,Sgb,Q00,Q01,Q11,Qb0,Qb1,Qbb
__device__ float g_E[BB*KK*NN];       // exp(logit)  (unnormalized attn)
__device__ float g_W[BB*KK*NN];       // E / sigma_v
__device__ float g_P[BB*KK*NN];       // W * mu_v
__device__ float h_qg[BB*KK*DD];      // (q @ w_mlp) * ln_kv_g
__device__ float h_qc[BB*KK*8];       // cb, sum(qg), qg.wg0, qg.wg1, qg.bg
__device__ float g_S[BB*KK];          // sum E (epilogue)
__device__ float g_Sp[BB*8*KK];       // partial sum E
__device__ float g_Pp[BB*8*KK];       // partial sum P
__device__ float g_Tp[BB*8*KK*DD];    // partials of W@fv
__device__ float g_Tq[KK*16*BB*DD];   // partials of W@ge
__device__ float g_Cp[BB*8*KK*CC];    // partials of attn@featc
__device__ float g_slot[BB*KK*DD];
__device__ float g_wmT[DD*DD];
__device__ float g_wresT[DD*DD];
__device__ float g_wihT[DD*3*DD];
__device__ float g_whhT[DD*3*DD];

// ---------------- precompute ----------------

__global__ void k_fgpos(const float* __restrict__ mask) {
    int k = blockIdx.x, t = threadIdx.x;
    float mx = 0.f, my = 0.f, s = 0.f;
    for (int n = t; n < NN; n += 256) {
        int h = n >> 6, w = n & 63;
        float m = mask[k*NN + n];
        mx += (-1.f + 2.f*w*(1.f/63.f))*m;
        my += (-1.f + 2.f*h*(1.f/63.f))*m;
        s += m;
    }
    __shared__ float sm[3][256];
    sm[0][t]=mx; sm[1][t]=my; sm[2][t]=s; __syncthreads();
    for (int o=128;o>0;o>>=1){
        if (t<o){ sm[0][t]+=sm[0][t+o]; sm[1][t]+=sm[1][t+o]; sm[2][t]+=sm[2][t+o]; }
        __syncthreads();
    }
    if (t==0){
        float inv = 1.f/(sm[2][0]+1e-5f);
        g_fg[k*2+0]=sm[0][0]*inv; g_fg[k*2+1]=sm[1][0]*inv;
    }
}

__global__ void k_lnc(const float* __restrict__ x, const float* __restrict__ g,
                      const float* __restrict__ b) {
    int idx = blockIdx.x*256 + threadIdx.x;
    int row = idx >> 4, lane = idx & 15;
    float v = x[row*CC + lane];
    float s = v;
    #pragma unroll
    for (int o=8;o>0;o>>=1) s += __shfl_xor_sync(0xffffffffu,s,o);
    float m = s*(1.f/16.f);
    float d = v-m;
    float s2 = d*d;
    #pragma unroll
    for (int o=8;o>0;o>>=1) s2 += __shfl_xor_sync(0xffffffffu,s2,o);
    float is = rsqrtf(s2*(1.f/16.f) + EPS_LN);
    g_featc[row*CC+lane] = d*is*g[lane] + b[lane];
}

// Fused: LN(feat), GEMM vs w_k/w_v, and per-row moment stats.
__global__ void k3_fkfv(const float* __restrict__ feat, const float* __restrict__ lng,
                        const float* __restrict__ lnb, const float* __restrict__ wk,
                        const float* __restrict__ wv, const float* __restrict__ wgr,
                        const float* __restrict__ bgr) {
    __shared__ float As[64][65];
    __shared__ float Ws[64][65];
    __shared__ float gS[64], bS[64], w0S[64], w1S[64], bgS[64];
    int t = threadIdx.x;
    int row0 = blockIdx.x*64;
    if (t < 64){
        gS[t]=lng[t]; bS[t]=lnb[t];
        w0S[t] = wgr[t*4+0]-wgr[t*4+2];
        w1S[t] = wgr[t*4+1]-wgr[t*4+3];
        bgS[t] = bgr[t];
    }
    const float4* ag = (const float4*)(feat + (size_t)row0*64);
    #pragma unroll
    for (int i=0;i<4;i++){
        int idx4 = t + i*256;
        float4 v = ag[idx4];
        int r = idx4 >> 4, d0 = (idx4 & 15)*4;
        As[r][d0]=v.x; As[r][d0+1]=v.y; As[r][d0+2]=v.z; As[r][d0+3]=v.w;
    }
    __syncthreads();
    {   // LayerNorm rows in place: 4 threads/row
        int r = t>>2, p = t&3;
        float s = 0.f;
        #pragma unroll
        for (int i=0;i<16;i++) s += As[r][p*16+i];
        s += __shfl_xor_sync(0xffffffffu,s,1);
        s += __shfl_xor_sync(0xffffffffu,s,2);
        float m = s*(1.f/64.f);
        float s2 = 0.f;
        #pragma unroll
        for (int i=0;i<16;i++){ float d = As[r][p*16+i]-m; s2 += d*d; }
        s2 += __shfl_xor_sync(0xffffffffu,s2,1);
        s2 += __shfl_xor_sync(0xffffffffu,s2,2);
        float is = rsqrtf(s2*(1.f/64.f) + EPS_LN);
        #pragma unroll
        for (int i=0;i<16;i++){
            int e = p*16+i;
            As[r][e] = (As[r][e]-m)*is*gS[e] + bS[e];
        }
    }
    int ty = t >> 4, tx = t & 15;
    int r0 = ty*4, c0 = tx*4;
    #pragma unroll
    for (int ph=0; ph<2; ph++){
        const float4* wg = (const float4*)(ph ? wv : wk);
        __syncthreads();
        #pragma unroll
        for (int i=0;i<4;i++){
            int idx4 = t + i*256;
            float4 v = wg[idx4];
            int r = idx4 >> 4, d0 = (idx4 & 15)*4;
            Ws[r][d0]=v.x; Ws[r][d0+1]=v.y; Ws[r][d0+2]=v.z; Ws[r][d0+3]=v.w;
        }
        __syncthreads();
        float acc[4][4] = {};
        #pragma unroll 4
        for (int d=0; d<64; d++){
            float a[4], w4[4];
            #pragma unroll
            for (int i=0;i<4;i++) a[i] = As[r0+i][d];
            #pragma unroll
            for (int j=0;j<4;j++) w4[j] = Ws[c0+j][d];
            #pragma unroll
            for (int i=0;i<4;i++)
                #pragma unroll
                for (int j=0;j<4;j++) acc[i][j] += a[i]*w4[j];
        }
        float* out = ph ? h_fv : h_fk;
        #pragma unroll
        for (int i=0;i<4;i++)
            *(float4*)(out + (size_t)(row0+r0+i)*64 + c0) =
                make_float4(acc[i][0],acc[i][1],acc[i][2],acc[i][3]);
        // row stats: Sum, SumSq, .wg0, .wg1, .bg — reduce across 16 tx lanes
        float st[4][5];
        #pragma unroll
        for (int i=0;i<4;i++){
            float s=0.f, s2=0.f, a0=0.f, a1=0.f, ab=0.f;
            #pragma unroll
            for (int j=0;j<4;j++){
                float v = acc[i][j]; int e = c0+j;
                s += v; s2 += v*v;
                a0 += v*w0S[e]; a1 += v*w1S[e]; ab += v*bgS[e];
            }
            st[i][0]=s; st[i][1]=s2; st[i][2]=a0; st[i][3]=a1; st[i][4]=ab;
        }
        #pragma unroll
        for (int o=1;o<16;o<<=1)
            #pragma unroll
            for (int i=0;i<4;i++)
                #pragma unroll
                for (int j=0;j<5;j++)
                    st[i][j] += __shfl_xor_sync(0xffffffffu, st[i][j], o);
        if (tx==0){
            float* stg = ph ? g_stV : g_stK;
            #pragma unroll
            for (int i=0;i<4;i++){
                float* p = stg + (size_t)(row0+r0+i)*8;
                p[0]=st[i][0]; p[1]=st[i][1]; p[2]=st[i][2]; p[3]=st[i][3]; p[4]=st[i][4];
            }
        }
    }
}

__global__ void k_slotinit(const float* __restrict__ noise, const float* __restrict__ mu,
                           const float* __restrict__ ls) {
    int i = blockIdx.x*256 + threadIdx.x;
    int d = i & 63;
    g_slot[i] = mu[d] + expf(ls[d]) * noise[i];
}

__global__ void k_transp(const float* __restrict__ wm, const float* __restrict__ wres,
                         const float* __restrict__ wih, const float* __restrict__ whh,
                         const float* __restrict__ wgr, const float* __restrict__ bgr) {
    int t = blockIdx.x*256 + threadIdx.x;
    if (t < 4096){
        int d = t >> 6, e = t & 63;
        g_wmT[e*64+d] = wm[t];
        g_wresT[e*64+d] = wres[t];
    }
    if (t < 192*64){
        int j = t >> 6, d = t & 63;
        g_wihT[d*192+j] = wih[t];
        g_whhT[d*192+j] = whh[t];
    }
    // grid-embed global scalars (block 0, threads 0..63)
    if (blockIdx.x==0){
        __shared__ float sm[2][9];
        int lt = threadIdx.x;
        float p9[9] = {};
        if (lt < 64){
            float w0 = wgr[lt*4+0]-wgr[lt*4+2];
            float w1 = wgr[lt*4+1]-wgr[lt*4+3];
            float bg = bgr[lt];
            p9[0]=w0; p9[1]=w1; p9[2]=bg;
            p9[3]=w0*w0; p9[4]=w0*w1; p9[5]=w1*w1;
            p9[6]=w0*bg; p9[7]=w1*bg; p9[8]=bg*bg;
        }
        if (lt < 64){
            #pragma unroll
            for (int o=16;o>0;o>>=1)
                #pragma unroll
                for (int j=0;j<9;j++) p9[j] += __shfl_xor_sync(0xffffffffu,p9[j],o);
            if ((lt&31)==0)
                #pragma unroll
                for (int j=0;j<9;j++) sm[lt>>5][j]=p9[j];
        }
        __syncthreads();
        if (lt < 9) g_gsc[lt] = sm[0][lt]+sm[1][lt];
    }
}

// ---------------- per-iteration ----------------

// standalone q (iteration 0 only)
__global__ void k3_q(const float* __restrict__ lnqg, const float* __restrict__ lnqb,
                     const float* __restrict__ wq,   const float* __restrict__ wm,
                     const float* __restrict__ bm,   const float* __restrict__ kvg,
                     const float* __restrict__ kvb,  const float* __restrict__ wgr,
                     const float* __restrict__ bgr) {
    __shared__ float WQ[64][65], WM[64][65];
    __shared__ float lnrow[4][64], qrow[4][64];
    __shared__ float red[4][2], red2[4][2];
    __shared__ float redq[4][2][5];
    int x = threadIdx.x, y = threadIdx.y;
    int t = y*64 + x;
    for (int i=t;i<4096;i+=256){ WQ[i>>6][i&63]=wq[i]; WM[i>>6][i&63]=wm[i]; }
    int row = blockIdx.x*4 + y;
    float sv = g_slot[row*64+x];
    float s = sv;
    #pragma unroll
    for (int o=16;o>0;o>>=1) s += __shfl_xor_sync(0xffffffffu,s,o);
    if ((x&31)==0) red[y][x>>5]=s;
    __syncthreads();
    float m = (red[y][0]+red[y][1])*(1.f/64.f);
    float d = sv - m;
    float s2 = d*d;
    #pragma unroll
    for (int o=16;o>0;o>>=1) s2 += __shfl_xor_sync(0xffffffffu,s2,o);
    if ((x&31)==0) red2[y][x>>5]=s2;
    __syncthreads();
    float is = rsqrtf((red2[y][0]+red2[y][1])*(1.f/64.f) + EPS_LN);
    lnrow[y][x] = d*is*lnqg[x] + lnqb[x];
    __syncthreads();
    float q = 0.f;
    #pragma unroll 8
    for (int j=0;j<64;j++) q += lnrow[y][j]*WQ[x][j];
    qrow[y][x] = q;
    __syncthreads();
    float qm = 0.f;
    #pragma unroll 8
    for (int j=0;j<64;j++) qm += qrow[y][j]*WM[j][x];
    float qgv = qm*kvg[x];
    h_qg[row*64+x] = qgv;
    float w0 = wgr[x*4+0]-wgr[x*4+2];
    float w1 = wgr[x*4+1]-wgr[x*4+3];
    float c[5] = { q*bm[x] + qm*kvb[x], qgv, qgv*w0, qgv*w1, qgv*bgr[x] };
    #pragma unroll
    for (int o=16;o>0;o>>=1)
        #pragma unroll
        for (int j=0;j<5;j++) c[j] += __shfl_xor_sync(0xffffffffu,c[j],o);
    if ((x&31)==0)
        #pragma unroll
        for (int j=0;j<5;j++) redq[y][x>>5][j]=c[j];
    __syncthreads();
    if (x < 5) h_qc[row*8+x] = redq[y][0][x]+redq[y][1][x];
}

// logits via folded stats: writes E, W, P
__global__ void k4_logits() {
    __shared__ float fkS[64][68];
    __shared__ float qgS[KK][64];
    __shared__ float qcS[KK][8];
    __shared__ float fgS[KK*2];
    __shared__ float gsc[9];
    int b = blockIdx.y, n0 = blockIdx.x*64, t = threadIdx.x;
    for (int i=t;i<KK*64;i+=256) qgS[i>>6][i&63] = h_qg[(b*KK + (i>>6))*64 + (i&63)];
    if (t < KK*8) qcS[t>>3][t&7] = h_qc[(b*KK + (t>>3))*8 + (t&7)];
    if (t < KK*2) fgS[t] = g_fg[t];
    if (t < 9) gsc[t] = g_gsc[t];
    const float4* fkg4 = (const float4*)(h_fk + (size_t)(b*NN+n0)*64);
    #pragma unroll
    for (int i=0;i<4;i++){
        int idx4 = t + i*256;
        float4 v = fkg4[idx4];
        int r = idx4>>4, c=(idx4&15)*4;
        fkS[r][c]=v.x; fkS[r][c+1]=v.y; fkS[r][c+2]=v.z; fkS[r][c+3]=v.w;
    }
    int n = t>>2, p = t&3;
    int ng = n0 + n;
    float stK[5], stV[5];
    if (p==0){
        const float* sk = g_stK + (size_t)(b*NN+ng)*8;
        const float* sv = g_stV + (size_t)(b*NN+ng)*8;
        #pragma unroll
        for (int i=0;i<5;i++){ stK[i]=sk[i]; stV[i]=sv[i]; }
    }
    float gx = -1.f + 2.f*(ng & 63)*(1.f/63.f);
    float gy = -1.f + 2.f*(ng >> 6)*(1.f/63.f);
    __syncthreads();
    for (int k=0;k<KK;k++){
        float dq = 0.f;
        #pragma unroll
        for (int i=0;i<16;i++) dq += qgS[k][p*16+i]*fkS[n][p*16+i];
        dq += __shfl_xor_sync(0xffffffffu,dq,1);
        dq += __shfl_xor_sync(0xffffffffu,dq,2);
        if (p==0){
            float r0 = gx - fgS[k*2+0];
            float r1 = gy - fgS[k*2+1];
            float Sge  = gsc[0]*r0 + gsc[1]*r1 + gsc[2];
            float Sge2 = gsc[3]*r0*r0 + 2.f*gsc[4]*r0*r1 + gsc[5]*r1*r1
                       + 2.f*gsc[6]*r0 + 2.f*gsc[7]*r1 + gsc[8];
            float fkge = stK[2]*r0 + stK[3]*r1 + stK[4];
            float su  = stK[0] + Sge;
            float su2 = stK[1] + 2.f*fkge + Sge2;
            float m   = su*(1.f/64.f);
            float var = su2*(1.f/64.f) - m*m;
            float is  = rsqrtf(var + EPS_LN);
            float dqf = dq + qcS[k][2]*r0 + qcS[k][3]*r1 + qcS[k][4];
            float lg  = SCALE*( is*(dqf - m*qcS[k][1]) + qcS[k][0] );
            float E   = __expf(lg);
            float fvge = stV[2]*r0 + stV[3]*r1 + stV[4];
            float svv  = stV[0] + Sge;
            float sv2  = stV[1] + 2.f*fvge + Sge2;
            float mv   = svv*(1.f/64.f);
            float varv = sv2*(1.f/64.f) - mv*mv;
            float isv  = rsqrtf(varv + EPS_LN);
            float W = E*isv;
            size_t idx = (size_t)(b*KK+k)*NN + ng;
            g_E[idx] = E;
            g_W[idx] = W;
            g_P[idx] = W*mv;
        }
    }
}

// W @ fv partials + per-(b,k) partial sums of E and P
__global__ void k4_updF() {
    __shared__ float wS[KK][512];
    __shared__ float part[4][KK][64];
    __shared__ float sredS[KK][8], sredP[KK][8];
    int seg = blockIdx.x, b = blockIdx.y, t = threadIdx.x;
    int nbase = seg*512;
    for (int i=t;i<KK*512;i+=256){
        int k=i>>9, n=i&511;
        wS[k][n] = g_W[(size_t)(b*KK+k)*NN + nbase+n];
    }
    __syncthreads();
    int e = t & 63, q = t >> 6;
    float acc[KK] = {};
    for (int n=q*128; n<q*128+128; n++){
        float fv = h_fv[(size_t)(b*NN+nbase+n)*64 + e];
        #pragma unroll
        for (int k=0;k<KK;k++) acc[k] += wS[k][n]*fv;
    }
    #pragma unroll
    for (int k=0;k<KK;k++) part[q][k][e] = acc[k];
    // E/P partial sums
    for (int k=0;k<KK;k++){
        size_t basek = (size_t)(b*KK+k)*NN + nbase;
        float se = g_E[basek + t] + g_E[basek + 256 + t];
        float pe = g_P[basek + t] + g_P[basek + 256 + t];
        #pragma unroll
        for (int o=16;o>0;o>>=1){
            se += __shfl_xor_sync(0xffffffffu,se,o);
            pe += __shfl_xor_sync(0xffffffffu,pe,o);
        }
        if ((t&31)==0){ sredS[k][t>>5]=se; sredP[k][t>>5]=pe; }
    }
    __syncthreads();
    for (int i=t;i<KK*64;i+=256){
        int k=i>>6, ee=i&63;
        float s = part[0][k][ee]+part[1][k][ee]+part[2][k][ee]+part[3][k][ee];
        g_Tp[(size_t)((b*8+seg)*KK+k)*64 + ee] = s;
    }
    if (t < KK){
        float s=0.f, pp=0.f;
        #pragma unroll
        for (int i=0;i<8;i++){ s += sredS[t][i]; pp += sredP[t][i]; }
        g_Sp[(b*8+seg)*KK+t] = s;
        g_Pp[(b*8+seg)*KK+t] = pp;
    }
}

// W @ ge partials, ge inline (16 segs -> 80 blocks)
__global__ void k4_updG(const float* __restrict__ wgr, const float* __restrict__ bgr) {
    __shared__ float wS[BB][256];
    __shared__ float part[BB][64];
    int seg = blockIdx.x, k = blockIdx.y, t = threadIdx.x;
    int nbase = seg*256;
    for (int i=t;i<BB*256;i+=256){
        int b=i>>8, n=i&255;
        wS[b][n] = g_W[(size_t)(b*KK+k)*NN + nbase+n];
    }
    for (int i=t;i<BB*64;i+=256) ((float*)part)[i] = 0.f;
    __syncthreads();
    int e = t & 63, q = t >> 6;
    float w0 = wgr[e*4+0] - wgr[e*4+2];
    float w1 = wgr[e*4+1] - wgr[e*4+3];
    float bg = bgr[e];
    float fgx = g_fg[k*2+0], fgy = g_fg[k*2+1];
    float acc[BB] = {};
    for (int n=q*64; n<q*64+64; n++){
        int ng = nbase + n;
        float r0 = (-1.f + 2.f*(ng & 63)*(1.f/63.f)) - fgx;
        float r1 = (-1.f + 2.f*(ng >> 6)*(1.f/63.f)) - fgy;
        float gv = w0*r0 + w1*r1 + bg;
        #pragma unroll
        for (int b=0;b<BB;b++) acc[b] += wS[b][n]*gv;
    }
    for (int qq=0;qq<4;qq++){
        if (q==qq){
            #pragma unroll
            for (int b=0;b<BB;b++) part[b][e] += acc[b];
        }
        __syncthreads();
    }
    for (int i=t;i<BB*64;i+=256){
        int b=i>>6, ee=i&63;
        g_Tq[(size_t)((k*16+seg)*BB+b)*64 + ee] = part[b][ee];
    }
}

// slot update (normalizes unnormalized sums) + fused next-iteration q
__global__ void k4_upd(const float* __restrict__ kvg, const float* __restrict__ kvb,
                       const float* __restrict__ bm,  const float* __restrict__ bih,
                       const float* __restrict__ bhh, const float* __restrict__ resg,
                       const float* __restrict__ resb,const float* __restrict__ bres,
                       const float* __restrict__ lnqg,const float* __restrict__ lnqb,
                       const float* __restrict__ wq,  const float* __restrict__ wm,
                       const float* __restrict__ wgr, const float* __restrict__ bgr) {
    __shared__ float WQ[64][65], WM[64][65];
    __shared__ float lnsum[4][64], upds[4][64], hps[4][64], lns[4][64];
    __shared__ float red[4][2], red2[4][2];
    __shared__ float redq[4][2][5];
    int x = threadIdx.x, y = threadIdx.y;
    int t = y*64 + x;
    for (int i=t;i<4096;i+=256){ WQ[i>>6][i&63]=wq[i]; WM[i>>6][i&63]=wm[i]; }
    int rrow = blockIdx.x*4 + y;
    int b = rrow/KK, k = rrow%KK;
    float S = 0.f, Pp = 0.f;
    #pragma unroll
    for (int seg=0;seg<8;seg++){
        S  += g_Sp[(b*8+seg)*KK+k];
        Pp += g_Pp[(b*8+seg)*KK+k];
    }
    float invS = 1.f/S;
    float T = 0.f;
    #pragma unroll
    for (int seg=0;seg<8;seg++)  T += g_Tp[(size_t)((b*8+seg)*KK+k)*64 + x];
    #pragma unroll
    for (int seg=0;seg<16;seg++) T += g_Tq[(size_t)((k*16+seg)*BB+b)*64 + x];
    T = (T - Pp)*invS;
    lnsum[y][x] = kvg[x]*T + kvb[x];
    float hp = g_slot[rrow*64+x];
    hps[y][x] = hp;
    __syncthreads();
    float upd = bm[x];
    #pragma unroll 8
    for (int e=0;e<64;e++) upd += g_wmT[e*64+x]*lnsum[y][e];
    upds[y][x] = upd;
    __syncthreads();
    float gir = bih[x], giz = bih[64+x], gin = bih[128+x];
    float ghr = bhh[x], ghz = bhh[64+x], ghn = bhh[128+x];
    #pragma unroll 4
    for (int d=0;d<64;d++){
        float u = upds[y][d], h = hps[y][d];
        const float* wiT = g_wihT + d*192;
        const float* whT = g_whhT + d*192;
        gir += wiT[x]*u;     giz += wiT[64+x]*u;  gin += wiT[128+x]*u;
        ghr += whT[x]*h;     ghz += whT[64+x]*h;  ghn += whT[128+x]*h;
    }
    float rg = 1.f/(1.f+expf(-(gir+ghr)));
    float z  = 1.f/(1.f+expf(-(giz+ghz)));
    float nn = tanhf(gin + rg*ghn);
    float hnew = (1.f-z)*nn + z*hp;
    float s = hnew;
    #pragma unroll
    for (int o=16;o>0;o>>=1) s += __shfl_xor_sync(0xffffffffu,s,o);
    if ((x&31)==0) red[y][x>>5]=s;
    __syncthreads();
    float m = (red[y][0]+red[y][1])*(1.f/64.f);
    float dd = hnew - m;
    float s2 = dd*dd;
    #pragma unroll
    for (int o=16;o>0;o>>=1) s2 += __shfl_xor_sync(0xffffffffu,s2,o);
    if ((x&31)==0) red2[y][x>>5]=s2;
    __syncthreads();
    float is = rsqrtf((red2[y][0]+red2[y][1])*(1.f/64.f) + EPS_LN);
    lns[y][x] = dd*is*resg[x] + resb[x];
    __syncthreads();
    float outv = bres[x] + hp;
    #pragma unroll 8
    for (int e=0;e<64;e++) outv += g_wresT[e*64+x]*lns[y][e];
    g_slot[rrow*64+x] = outv;
    // ---- fused q for next iteration ----
    __syncthreads();
    float sq = outv;
    #pragma unroll
    for (int o=16;o>0;o>>=1) sq += __shfl_xor_sync(0xffffffffu,sq,o);
    if ((x&31)==0) red[y][x>>5]=sq;
    __syncthreads();
    float mq = (red[y][0]+red[y][1])*(1.f/64.f);
    float dq = outv - mq;
    float sq2 = dq*dq;
    #pragma unroll
    for (int o=16;o>0;o>>=1) sq2 += __shfl_xor_sync(0xffffffffu,sq2,o);
    if ((x&31)==0) red2[y][x>>5]=sq2;
    __syncthreads();
    float isq = rsqrtf((red2[y][0]+red2[y][1])*(1.f/64.f) + EPS_LN);
    lnsum[y][x] = dq*isq*lnqg[x] + lnqb[x];
    __syncthreads();
    float qv = 0.f;
    #pragma unroll 8
    for (int j=0;j<64;j++) qv += lnsum[y][j]*WQ[x][j];
    upds[y][x] = qv;
    __syncthreads();
    float qm = 0.f;
    #pragma unroll 8
    for (int j=0;j<64;j++) qm += upds[y][j]*WM[j][x];
    float qgv = qm*kvg[x];
    h_qg[rrow*64+x] = qgv;
    float w0 = wgr[x*4+0]-wgr[x*4+2];
    float w1 = wgr[x*4+1]-wgr[x*4+3];
    float c[5] = { qv*bm[x] + qm*kvb[x], qgv, qgv*w0, qgv*w1, qgv*bgr[x] };
    #pragma unroll
    for (int o=16;o>0;o>>=1)
        #pragma unroll
        for (int j=0;j<5;j++) c[j] += __shfl_xor_sync(0xffffffffu,c[j],o);
    if ((x&31)==0)
        #pragma unroll
        for (int j=0;j<5;j++) redq[y][x>>5][j]=c[j];
    __syncthreads();
    if (x < 5) h_qc[rrow*8+x] = redq[y][0][x]+redq[y][1][x];
}

// ---------------- epilogue ----------------

__global__ void k_Sred() {
    int r = blockIdx.x, t = threadIdx.x;
    size_t base = (size_t)r*NN;
    float s = 0.f;
    #pragma unroll
    for (int j=0;j<16;j++) s += g_E[base + j*256 + t];
    __shared__ float sm[8];
    #pragma unroll
    for (int o=16;o>0;o>>=1) s += __shfl_xor_sync(0xffffffffu,s,o);
    if ((t&31)==0) sm[t>>5]=s;
    __syncthreads();
    if (t==0){
        float tot=0.f;
        #pragma unroll
        for (int i=0;i<8;i++) tot += sm[i];
        g_S[r]=tot;
    }
}

__global__ void k_color() {
    __shared__ float aS[KK][512];
    __shared__ float part2[16][KK][CC];
    __shared__ float iS[KK];
    int seg = blockIdx.x, b = blockIdx.y, t = threadIdx.x;
    int nbase = seg*512;
    if (t < KK) iS[t] = 1.f/g_S[b*KK+t];
    __syncthreads();
    for (int i=t;i<KK*512;i+=256){
        int k=i>>9, n=i&511;
        aS[k][n] = g_E[(size_t)(b*KK+k)*NN + nbase+n]*iS[k];
    }
    __syncthreads();
    int c = t & 15, q = t >> 4;
    float acc[KK] = {};
    for (int n=q*32; n<q*32+32; n++){
        float fc = g_featc[(size_t)(b*NN+nbase+n)*CC + c];
        #pragma unroll
        for (int k=0;k<KK;k++) acc[k] += aS[k][n]*fc;
    }
    #pragma unroll
    for (int k=0;k<KK;k++) part2[q][k][c] = acc[k];
    __syncthreads();
    if (t < KK*CC){
        int k = t>>4, cc = t&15;
        float s = 0.f;
        #pragma unroll
        for (int qq=0;qq<16;qq++) s += part2[qq][k][cc];
        g_Cp[(size_t)((b*8+seg)*KK+k)*CC + cc] = s;
    }
}

__global__ void k_outslot(float* __restrict__ out) {
    int t = threadIdx.x;
    for (int i=t; i<80*80; i+=256){
        int r = i/80, d = i%80;
        float v;
        if (d < 64) v = g_slot[r*64+d];
        else {
            int c = d-64, b = r/KK, k = r%KK;
            v = 0.f;
            #pragma unroll
            for (int seg=0;seg<8;seg++) v += g_Cp[(size_t)((b*8+seg)*KK+k)*CC + c];
        }
        out[i] = v;
    }
    if (t < 160){
        int r = t>>1, k = r%KK;
        out[6400 + t] = g_fg[k*2 + (t&1)];
    }
}

__global__ void k_attnnorm(float* __restrict__ out) {
    int k = blockIdx.x, b = blockIdx.y, r = b*KK+k, t = threadIdx.x;
    size_t base = (size_t)r*NN;
    float invS = 1.f/g_S[r];
    float mn = 1e30f, mx = -1e30f;
    float a[16];
    #pragma unroll
    for (int j=0;j<16;j++){
        a[j] = g_E[base + j*256 + t]*invS;
        mn = fminf(mn, a[j]); mx = fmaxf(mx, a[j]);
    }
    __shared__ float sred[8], sred2[8];
    #pragma unroll
    for (int o=16;o>0;o>>=1){
        mn = fminf(mn, __shfl_xor_sync(0xffffffffu,mn,o));
        mx = fmaxf(mx, __shfl_xor_sync(0xffffffffu,mx,o));
    }
    if ((t&31)==0){ sred[t>>5]=mn; sred2[t>>5]=mx; }
    __syncthreads();
    mn = sred[0]; mx = sred2[0];
    #pragma unroll
    for (int i=1;i<8;i++){ mn = fminf(mn, sred[i]); mx = fmaxf(mx, sred2[i]); }
    float inv = 1.f/(mx-mn+1e-5f);
    #pragma unroll
    for (int j=0;j<16;j++)
        out[6560 + base + j*256 + t] = (a[j]-mn)*inv;
}

// ---------------- launch ----------------

extern "C" void kernel_launch(void* const* d_in, const int* in_sizes, int n_in,
                              void* d_out, int out_size) {
    const float* feat  = (const float*)d_in[0];
    const float* featc = (const float*)d_in[1];
    const float* mask  = (const float*)d_in[2];
    const float* noise = (const float*)d_in[3];
    const float* mu    = (const float*)d_in[4];
    const float* ls    = (const float*)d_in[5];
    const float* wgrid = (const float*)d_in[6];
    const float* bgrid = (const float*)d_in[7];
    const float* wk    = (const float*)d_in[8];
    const float* wv    = (const float*)d_in[9];
    const float* kvg   = (const float*)d_in[10];
    const float* kvb   = (const float*)d_in[11];
    const float* wmlp  = (const float*)d_in[12];
    const float* bmlp  = (const float*)d_in[13];
    const float* qg_   = (const float*)d_in[14];
    const float* qb_   = (const float*)d_in[15];
    const float* wq    = (const float*)d_in[16];
    const float* wih   = (const float*)d_in[17];
    const float* whh   = (const float*)d_in[18];
    const float* bih   = (const float*)d_in[19];
    const float* bhh   = (const float*)d_in[20];
    const float* fg_   = (const float*)d_in[21];
    const float* fb_   = (const float*)d_in[22];
    const float* cg_   = (const float*)d_in[23];
    const float* cb_   = (const float*)d_in[24];
    const float* rg_   = (const float*)d_in[25];
    const float* rb_   = (const float*)d_in[26];
    const float* wres  = (const float*)d_in[27];
    const float* bres  = (const float*)d_in[28];
    float* out = (float*)d_out;

    k_fgpos<<<KK,256>>>(mask);
    k_lnc<<<BN/16, 256>>>(featc, cg_, cb_);
    k3_fkfv<<<BN/64, 256>>>(feat, fg_, fb_, wk, wv, wgrid, bgrid);
    k_slotinit<<<BB*KK*DD/256, 256>>>(noise, mu, ls);
    k_transp<<<48, 256>>>(wmlp, wres, wih, whh, wgrid, bgrid);
    k3_q<<<20, dim3(64,4)>>>(qg_, qb_, wq, wmlp, bmlp, kvg, kvb, wgrid, bgrid);

    for (int it=0; it<4; it++){
        k4_logits<<<dim3(NN/64, BB), 256>>>();
        if (it < 3){
            k4_updF<<<dim3(8, BB), 256>>>();
            k4_updG<<<dim3(16, KK), 256>>>(wgrid, bgrid);
            k4_upd<<<20, dim3(64,4)>>>(kvg, kvb, bmlp, bih, bhh, rg_, rb_, bres,
                                       qg_, qb_, wq, wmlp, wgrid, bgrid);
        }
    }
    k_Sred<<<BB*KK, 256>>>();
    k_color<<<dim3(8, BB), 256>>>();
    k_attnnorm<<<dim3(KK, BB), 256>>>(out);
    k_outslot<<<1, 256>>>(out);
}